// round 9
// baseline (speedup 1.0000x reference)
#include <cuda_runtime.h>
#include <math.h>

// Problem constants
#define N_TOK   8192          // B*T = 4*2048
#define CDIM    1024
#define NEXP    8
#define DFF     4096
#define TOPK    2

// GEMM tiling
#define BM 128
#define BN 128
#define BK 32
#define MAX_TILES (2*N_TOK/BM + NEXP)          // 136 upper bound on row tiles
#define SLOT_CAP  (2*N_TOK + NEXP*BM)          // 17408 (per-expert 128-padding)

// ---------------- scratch (static device globals; no allocation) ----------------
__device__ float g_h[(size_t)SLOT_CAP * DFF];   // GEMM1 output (gelu'd), fp32
__device__ float g_y[(size_t)SLOT_CAP * CDIM];  // GEMM2 output, fp32
__device__ int   g_counts[NEXP];
__device__ int   g_poff[NEXP];
__device__ int   g_tile_e[MAX_TILES];
__device__ int   g_tile_row0[MAX_TILES];
__device__ int   g_tile_rowend[MAX_TILES];
__device__ int   g_ntiles;
__device__ int   g_slot_token[SLOT_CAP];
__device__ int   g_exp[2*N_TOK];
__device__ float g_wt[2*N_TOK];
__device__ int   g_rank[2*N_TOK];
__device__ int   g_tok_slot[2*N_TOK];

// ---------------- helpers ----------------
__device__ __forceinline__ unsigned f2tf(float x) {
    unsigned u;
    asm("cvt.rna.tf32.f32 %0, %1;" : "=r"(u) : "f"(x));
    return u;
}

__device__ __forceinline__ void mma8(float* d, const unsigned* a, const unsigned* b) {
    asm volatile(
        "mma.sync.aligned.m16n8k8.row.col.f32.tf32.tf32.f32 "
        "{%0,%1,%2,%3}, {%4,%5,%6,%7}, {%8,%9}, {%0,%1,%2,%3};"
        : "+f"(d[0]), "+f"(d[1]), "+f"(d[2]), "+f"(d[3])
        : "r"(a[0]), "r"(a[1]), "r"(a[2]), "r"(a[3]), "r"(b[0]), "r"(b[1]));
}

__device__ __forceinline__ float gelu_exact(float v) {
    return 0.5f * v * (1.0f + erff(v * 0.70710678118654752440f));
}

// ---------------- kernel 0: zero per-expert counters ----------------
__global__ void k_init() {
    if (threadIdx.x < NEXP) g_counts[threadIdx.x] = 0;
}

// ---------------- kernel 1: router (warp per token) ----------------
__global__ void k_router(const float* __restrict__ x,
                         const float* __restrict__ rw,
                         const float* __restrict__ rb) {
    int tok  = (blockIdx.x * blockDim.x + threadIdx.x) >> 5;
    int lane = threadIdx.x & 31;
    if (tok >= N_TOK) return;

    const float* xr = x + (size_t)tok * CDIM;
    float acc[NEXP];
#pragma unroll
    for (int e = 0; e < NEXP; e++) acc[e] = 0.f;

    for (int c = lane; c < CDIM; c += 32) {
        float xv = xr[c];
        float4 wa = *(const float4*)(rw + c * NEXP);
        float4 wb = *(const float4*)(rw + c * NEXP + 4);
        acc[0] += xv * wa.x; acc[1] += xv * wa.y;
        acc[2] += xv * wa.z; acc[3] += xv * wa.w;
        acc[4] += xv * wb.x; acc[5] += xv * wb.y;
        acc[6] += xv * wb.z; acc[7] += xv * wb.w;
    }
#pragma unroll
    for (int off = 16; off > 0; off >>= 1)
#pragma unroll
        for (int e = 0; e < NEXP; e++)
            acc[e] += __shfl_xor_sync(0xffffffffu, acc[e], off);

    if (lane == 0) {
        float mx = -1e30f;
#pragma unroll
        for (int e = 0; e < NEXP; e++) { acc[e] += rb[e]; mx = fmaxf(mx, acc[e]); }
        float p[NEXP]; float s = 0.f;
#pragma unroll
        for (int e = 0; e < NEXP; e++) { p[e] = expf(acc[e] - mx); s += p[e]; }
        float inv = 1.0f / s;
#pragma unroll
        for (int e = 0; e < NEXP; e++) p[e] *= inv;

        // top-2, ties -> lowest index (matches lax.top_k)
        int e0 = 0; float v0 = p[0];
#pragma unroll
        for (int e = 1; e < NEXP; e++) if (p[e] > v0) { v0 = p[e]; e0 = e; }
        int e1 = -1; float v1 = -1.f;
#pragma unroll
        for (int e = 0; e < NEXP; e++)
            if (e != e0 && p[e] > v1) { v1 = p[e]; e1 = e; }

        int r0 = atomicAdd(&g_counts[e0], 1);
        int r1 = atomicAdd(&g_counts[e1], 1);
        g_exp[2 * tok]     = e0; g_wt[2 * tok]     = v0; g_rank[2 * tok]     = r0;
        g_exp[2 * tok + 1] = e1; g_wt[2 * tok + 1] = v1; g_rank[2 * tok + 1] = r1;
    }
}

// ---------------- kernel 2: build padded offsets + tile table ----------------
__global__ void k_sched() {
    int off = 0, nt = 0;
    for (int e = 0; e < NEXP; e++) {
        g_poff[e] = off;
        int c = g_counts[e];
        int tiles = (c + BM - 1) / BM;
        for (int t = 0; t < tiles; t++) {
            g_tile_e[nt] = e;
            g_tile_row0[nt] = off + t * BM;
            g_tile_rowend[nt] = off + c;
            nt++;
        }
        off += tiles * BM;
    }
    g_ntiles = nt;
}

// ---------------- kernel 3: scatter token->slot ----------------
__global__ void k_scatter() {
    int i = blockIdx.x * blockDim.x + threadIdx.x;
    if (i >= 2 * N_TOK) return;
    int e = g_exp[i];
    int slot = g_poff[e] + g_rank[i];
    g_slot_token[slot] = i >> 1;
    g_tok_slot[i] = slot;
}

// ---------------- grouped GEMM: TF32 mma.sync, 128x128x32 tiles ----------------
// FIRST=true : A = gathered x rows [*,CDIM],  W = w1[E][CDIM][DFF],  out = gelu(..)+b1 -> g_h
// FIRST=false: A = g_h rows [*,DFF],          W = w2[E][DFF][CDIM],  out = ..+b2      -> g_y
template <int KDIM, int NDIM, bool FIRST>
__global__ void __launch_bounds__(256)
k_gemm(const float* __restrict__ Xsrc,
       const float* __restrict__ W,
       const float* __restrict__ bias) {
    int tile = blockIdx.x;
    if (tile >= g_ntiles) return;
    int e      = g_tile_e[tile];
    int row0   = g_tile_row0[tile];
    int rowend = g_tile_rowend[tile];
    int n0     = blockIdx.y * BN;

    __shared__ unsigned As[BM][BK + 4];   // +4 pad: conflict-free frag loads
    __shared__ unsigned Bs[BK][BN + 8];   // +8 pad: conflict-free frag loads

    int tid  = threadIdx.x;
    int lane = tid & 31, warp = tid >> 5;
    int wm = warp & 3;        // 4 warps along M -> 32 rows each
    int wn = warp >> 2;       // 2 warps along N -> 64 cols each
    int g  = lane >> 2, tg = lane & 3;

    // A staging: each thread owns 4 rows (tid/8 + i*32), 4 consecutive floats.
    int arow = tid >> 3;            // 0..31
    int acol = (tid & 7) * 4;       // 0..28
    const float* aptr[4];
#pragma unroll
    for (int i = 0; i < 4; i++) {
        int grow = row0 + arow + i * 32;
        const float* base;
        if (FIRST) {
            int t = (grow < rowend) ? g_slot_token[grow] : 0;
            base = Xsrc + (size_t)t * KDIM;
        } else {
            base = g_h + (size_t)grow * KDIM;
        }
        aptr[i] = base + acol;
    }

    const float* wp = W + (size_t)e * KDIM * NDIM;
    int bcol = (tid & 31) * 4;      // 0..124
    int bk0  = tid >> 5;            // 0..7

    float acc[2][8][4];
#pragma unroll
    for (int mi = 0; mi < 2; mi++)
#pragma unroll
        for (int ni = 0; ni < 8; ni++)
#pragma unroll
            for (int q = 0; q < 4; q++) acc[mi][ni][q] = 0.f;

    for (int kt = 0; kt < KDIM; kt += BK) {
        // stage A (convert to tf32 at store)
#pragma unroll
        for (int i = 0; i < 4; i++) {
            float4 v = *(const float4*)(aptr[i] + kt);
            uint4 u;
            u.x = f2tf(v.x); u.y = f2tf(v.y); u.z = f2tf(v.z); u.w = f2tf(v.w);
            *(uint4*)&As[arow + i * 32][acol] = u;
        }
        // stage B
#pragma unroll
        for (int i = 0; i < 4; i++) {
            int bk = bk0 + i * 8;
            float4 v = *(const float4*)(wp + (size_t)(kt + bk) * NDIM + n0 + bcol);
            uint4 u;
            u.x = f2tf(v.x); u.y = f2tf(v.y); u.z = f2tf(v.z); u.w = f2tf(v.w);
            *(uint4*)&Bs[bk][bcol] = u;
        }
        __syncthreads();

#pragma unroll
        for (int kk = 0; kk < BK; kk += 8) {
            unsigned a[2][4], b[8][2];
#pragma unroll
            for (int mi = 0; mi < 2; mi++) {
                int m = wm * 32 + mi * 16;
                a[mi][0] = As[m + g][kk + tg];
                a[mi][1] = As[m + g + 8][kk + tg];
                a[mi][2] = As[m + g][kk + tg + 4];
                a[mi][3] = As[m + g + 8][kk + tg + 4];
            }
#pragma unroll
            for (int ni = 0; ni < 8; ni++) {
                int n = wn * 64 + ni * 8 + g;
                b[ni][0] = Bs[kk + tg][n];
                b[ni][1] = Bs[kk + tg + 4][n];
            }
#pragma unroll
            for (int mi = 0; mi < 2; mi++)
#pragma unroll
                for (int ni = 0; ni < 8; ni++)
                    mma8(acc[mi][ni], a[mi], b[ni]);
        }
        __syncthreads();
    }

    // epilogue: bias (+ exact gelu for GEMM1), write fp32
    float* Outp = FIRST ? g_h : g_y;
    const float* bp = bias + (size_t)e * NDIM;
#pragma unroll
    for (int mi = 0; mi < 2; mi++) {
#pragma unroll
        for (int rr = 0; rr < 2; rr++) {
            int row = row0 + wm * 32 + mi * 16 + g + rr * 8;
#pragma unroll
            for (int ni = 0; ni < 8; ni++) {
                int col = n0 + wn * 64 + ni * 8 + 2 * tg;
                float v0 = acc[mi][ni][2 * rr]     + bp[col];
                float v1 = acc[mi][ni][2 * rr + 1] + bp[col + 1];
                if (FIRST) { v0 = gelu_exact(v0); v1 = gelu_exact(v1); }
                float2 o; o.x = v0; o.y = v1;
                *(float2*)(Outp + (size_t)row * NDIM + col) = o;
            }
        }
    }
}

// ---------------- kernel 6: per-token combine ----------------
__global__ void k_combine(float* __restrict__ out) {
    int i = blockIdx.x * blockDim.x + threadIdx.x;
    if (i >= N_TOK * (CDIM / 4)) return;
    int t = i / (CDIM / 4);
    int c = (i % (CDIM / 4)) * 4;
    int s0 = g_tok_slot[2 * t], s1 = g_tok_slot[2 * t + 1];
    float w0 = g_wt[2 * t], w1 = g_wt[2 * t + 1];
    float4 y0 = *(const float4*)(g_y + (size_t)s0 * CDIM + c);
    float4 y1 = *(const float4*)(g_y + (size_t)s1 * CDIM + c);
    float4 o;
    o.x = w0 * y0.x + w1 * y1.x;
    o.y = w0 * y0.y + w1 * y1.y;
    o.z = w0 * y0.z + w1 * y1.z;
    o.w = w0 * y0.w + w1 * y1.w;
    *(float4*)(out + (size_t)t * CDIM + c) = o;
}

// ---------------- launch ----------------
extern "C" void kernel_launch(void* const* d_in, const int* in_sizes, int n_in,
                              void* d_out, int out_size) {
    const float* x  = (const float*)d_in[0];
    const float* rw = (const float*)d_in[1];
    const float* rb = (const float*)d_in[2];
    const float* w1 = (const float*)d_in[3];
    const float* b1 = (const float*)d_in[4];
    const float* w2 = (const float*)d_in[5];
    const float* b2 = (const float*)d_in[6];
    float* out = (float*)d_out;

    k_init<<<1, 32>>>();
    k_router<<<N_TOK / 8, 256>>>(x, rw, rb);          // 8 warps/block
    k_sched<<<1, 1>>>();
    k_scatter<<<(2 * N_TOK + 255) / 256, 256>>>();
    k_gemm<CDIM, DFF,  true ><<<dim3(MAX_TILES, DFF  / BN), 256>>>(x,       w1, b1);
    k_gemm<DFF,  CDIM, false><<<dim3(MAX_TILES, CDIM / BN), 256>>>(nullptr, w2, b2);
    k_combine<<<(N_TOK * (CDIM / 4) + 255) / 256, 256>>>(out);
}

// round 12
// speedup vs baseline: 3.4796x; 3.4796x over previous
#include <cuda_runtime.h>
#include <cuda_fp16.h>
#include <math.h>
#include <stdint.h>

// -------------------- problem constants --------------------
#define N_TOK   8192
#define CDIM    1024
#define NEXP    8
#define DFF     4096

// -------------------- tiling --------------------
#define BM 128
#define BN 128
#define BKH 64                                  // halfs per k-tile = 128 bytes
#define MAX_TILES (2*N_TOK/BM + NEXP)           // 136
#define SLOT_CAP  (2*N_TOK + NEXP*BM)           // 17408

#define A_STAGE 16384                           // 128 rows * 128 B
#define B_STAGE 16384
#define SMEM_DYN (2*A_STAGE + 2*B_STAGE)        // 65536

// -------------------- scratch (static device globals; no allocation) ----------
__device__ __half g_A0h[(size_t)SLOT_CAP * CDIM];            // gathered x, fp16
__device__ __half g_h  [(size_t)SLOT_CAP * DFF];             // gelu(h), fp16
__device__ float  g_y  [(size_t)SLOT_CAP * CDIM];            // expert out, fp32
__device__ __half g_w1t[(size_t)NEXP * (size_t)DFF * CDIM];  // [E][DFF][CDIM] K-major
__device__ __half g_w2t[(size_t)NEXP * (size_t)CDIM * DFF];  // [E][CDIM][DFF] K-major
__device__ int   g_counts[NEXP];
__device__ int   g_poff[NEXP];
__device__ int   g_tile_e[MAX_TILES];
__device__ int   g_tile_row0[MAX_TILES];
__device__ int   g_ntiles;
__device__ int   g_slot_token[SLOT_CAP];
__device__ int   g_exp[2*N_TOK];
__device__ float g_wt[2*N_TOK];
__device__ int   g_rank[2*N_TOK];
__device__ int   g_tok_slot[2*N_TOK];

// -------------------- helpers --------------------
__device__ __forceinline__ uint32_t smem_u32(const void* p) {
    uint32_t a;
    asm("{ .reg .u64 t; cvta.to.shared.u64 t, %1; cvt.u32.u64 %0, t; }" : "=r"(a) : "l"(p));
    return a;
}
__device__ __forceinline__ uint32_t swz(uint32_t off) { return off ^ ((off >> 3) & 0x70); }

__device__ __forceinline__ void cpa16(uint32_t dst, const void* src) {
    asm volatile("cp.async.cg.shared.global [%0], [%1], 16;" :: "r"(dst), "l"(src));
}
__device__ __forceinline__ void cpa_commit() { asm volatile("cp.async.commit_group;" ::: "memory"); }
template <int N> __device__ __forceinline__ void cpa_wait() {
    asm volatile("cp.async.wait_group %0;" :: "n"(N) : "memory");
}
__device__ __forceinline__ void ldsm4(uint32_t& r0, uint32_t& r1, uint32_t& r2, uint32_t& r3,
                                      uint32_t addr) {
    asm volatile("ldmatrix.sync.aligned.m8n8.x4.shared.b16 {%0,%1,%2,%3}, [%4];"
                 : "=r"(r0), "=r"(r1), "=r"(r2), "=r"(r3) : "r"(addr));
}
__device__ __forceinline__ void mma16(float* d, const uint32_t* a, uint32_t b0, uint32_t b1) {
    asm volatile(
        "mma.sync.aligned.m16n8k16.row.col.f32.f16.f16.f32 "
        "{%0,%1,%2,%3}, {%4,%5,%6,%7}, {%8,%9}, {%0,%1,%2,%3};"
        : "+f"(d[0]), "+f"(d[1]), "+f"(d[2]), "+f"(d[3])
        : "r"(a[0]), "r"(a[1]), "r"(a[2]), "r"(a[3]), "r"(b0), "r"(b1));
}
__device__ __forceinline__ float gelu_exact(float v) {
    return 0.5f * v * (1.0f + erff(v * 0.70710678118654752440f));
}

// -------------------- small kernels --------------------
__global__ void k_init() {
    int i = blockIdx.x * blockDim.x + threadIdx.x;
    if (i < SLOT_CAP) g_slot_token[i] = -1;
    if (i < NEXP) g_counts[i] = 0;
}

__global__ void k_router(const float* __restrict__ x,
                         const float* __restrict__ rw,
                         const float* __restrict__ rb) {
    int tok  = (blockIdx.x * blockDim.x + threadIdx.x) >> 5;
    int lane = threadIdx.x & 31;
    if (tok >= N_TOK) return;
    const float* xr = x + (size_t)tok * CDIM;
    float acc[NEXP];
#pragma unroll
    for (int e = 0; e < NEXP; e++) acc[e] = 0.f;
    for (int c = lane; c < CDIM; c += 32) {
        float xv = xr[c];
        float4 wa = *(const float4*)(rw + c * NEXP);
        float4 wb = *(const float4*)(rw + c * NEXP + 4);
        acc[0] += xv * wa.x; acc[1] += xv * wa.y;
        acc[2] += xv * wa.z; acc[3] += xv * wa.w;
        acc[4] += xv * wb.x; acc[5] += xv * wb.y;
        acc[6] += xv * wb.z; acc[7] += xv * wb.w;
    }
#pragma unroll
    for (int off = 16; off > 0; off >>= 1)
#pragma unroll
        for (int e = 0; e < NEXP; e++)
            acc[e] += __shfl_xor_sync(0xffffffffu, acc[e], off);
    if (lane == 0) {
        float mx = -1e30f;
#pragma unroll
        for (int e = 0; e < NEXP; e++) { acc[e] += rb[e]; mx = fmaxf(mx, acc[e]); }
        float p[NEXP]; float s = 0.f;
#pragma unroll
        for (int e = 0; e < NEXP; e++) { p[e] = expf(acc[e] - mx); s += p[e]; }
        float inv = 1.0f / s;
#pragma unroll
        for (int e = 0; e < NEXP; e++) p[e] *= inv;
        int e0 = 0; float v0 = p[0];
#pragma unroll
        for (int e = 1; e < NEXP; e++) if (p[e] > v0) { v0 = p[e]; e0 = e; }
        int e1 = -1; float v1 = -1.f;
#pragma unroll
        for (int e = 0; e < NEXP; e++)
            if (e != e0 && p[e] > v1) { v1 = p[e]; e1 = e; }
        int r0 = atomicAdd(&g_counts[e0], 1);
        int r1 = atomicAdd(&g_counts[e1], 1);
        g_exp[2*tok]   = e0; g_wt[2*tok]   = v0; g_rank[2*tok]   = r0;
        g_exp[2*tok+1] = e1; g_wt[2*tok+1] = v1; g_rank[2*tok+1] = r1;
    }
}

__global__ void k_sched() {
    int off = 0, nt = 0;
    for (int e = 0; e < NEXP; e++) {
        g_poff[e] = off;
        int c = g_counts[e];
        int tiles = (c + BM - 1) / BM;
        for (int t = 0; t < tiles; t++) {
            g_tile_e[nt] = e;
            g_tile_row0[nt] = off + t * BM;
            nt++;
        }
        off += tiles * BM;
    }
    g_ntiles = nt;
}

__global__ void k_scatter() {
    int i = blockIdx.x * blockDim.x + threadIdx.x;
    if (i >= 2 * N_TOK) return;
    int e = g_exp[i];
    int slot = g_poff[e] + g_rank[i];
    g_slot_token[slot] = i >> 1;
    g_tok_slot[i] = slot;
}

// gather tokens into padded fp16 A0; pad rows -> 0
__global__ void k_gather(const float* __restrict__ x) {
    int s = blockIdx.x;
    int t = g_slot_token[s];
    uint2* dst = (uint2*)(g_A0h + (size_t)s * CDIM) + threadIdx.x;   // 4 halfs each
    if (t < 0) {
        uint2 z; z.x = 0u; z.y = 0u;
        *dst = z;
    } else {
        float4 v = ((const float4*)(x + (size_t)t * CDIM))[threadIdx.x];
        __half2 h01 = __floats2half2_rn(v.x, v.y);
        __half2 h23 = __floats2half2_rn(v.z, v.w);
        uint2 o;
        o.x = *(uint32_t*)&h01;
        o.y = *(uint32_t*)&h23;
        *dst = o;
    }
}

// transpose+convert [E][K][N] fp32 -> [E][N][K] fp16
__global__ void k_wcvt(const float* __restrict__ src, __half* __restrict__ dst,
                       int K, int N) {
    __shared__ float t[32][33];
    int e = blockIdx.z;
    const float* S = src + (size_t)e * K * N;
    __half* D = dst + (size_t)e * K * N;
    int n0 = blockIdx.x * 32, k0 = blockIdx.y * 32;
    int tx = threadIdx.x, ty = threadIdx.y;
#pragma unroll
    for (int i = 0; i < 32; i += 8)
        t[ty + i][tx] = S[(size_t)(k0 + ty + i) * N + n0 + tx];
    __syncthreads();
#pragma unroll
    for (int i = 0; i < 32; i += 8)
        D[(size_t)(n0 + ty + i) * K + k0 + tx] = __float2half_rn(t[tx][ty + i]);
}

// -------------------- fp16 grouped GEMM (mma.sync m16n8k16, ldmatrix, cp.async) ----
// D[128,128] = A[128,K] @ Bt[128,K]^T ; A,Bt fp16 K-major; fp32 accum.
template <int KDIM, int NDIM, bool FIRST>
__global__ void __launch_bounds__(256)
hgemm(const __half* __restrict__ Ag,     // rows = slots, K-contig
      const __half* __restrict__ Bt,     // [E][NDIM][KDIM] K-contig
      const float* __restrict__ bias,    // [E][NDIM]
      void* __restrict__ OutP)
{
    int tile = blockIdx.x;
    if (tile >= g_ntiles) return;
    int e    = g_tile_e[tile];
    int row0 = g_tile_row0[tile];
    int n0   = blockIdx.y * BN;

    extern __shared__ __align__(1024) char smem[];
    uint32_t sb = smem_u32(smem);
    int tid = threadIdx.x;
    int lane = tid & 31, warp = tid >> 5;
    int wm = warp & 3;        // 4 warps along M -> 32 rows
    int wn = warp >> 2;       // 2 warps along N -> 64 cols
    int g = lane >> 2, tg = lane & 3;

    const __half* Arow = Ag + (size_t)row0 * KDIM;
    const __half* Brow = Bt + ((size_t)e * NDIM + n0) * KDIM;

    // stage loader: 128 A rows + 128 B rows, 128B each, 16B chunks -> 2048 cp / 256 thr
    auto load_stage = [&](int s, int kt) {
#pragma unroll
        for (int j = 0; j < 8; j++) {
            int idx = tid + j * 256;
            int r = idx >> 3;
            int c = (idx & 7) * 16;                       // byte offset in 128B row
            if (r < 128) {
                const char* src = (const char*)(Arow + (size_t)r * KDIM + kt) + c;
                cpa16(sb + s * A_STAGE + swz((uint32_t)(r * 128 + c)), src);
            } else {
                int rb2 = r - 128;
                const char* src = (const char*)(Brow + (size_t)rb2 * KDIM + kt) + c;
                cpa16(sb + 2 * A_STAGE + s * B_STAGE + swz((uint32_t)(rb2 * 128 + c)), src);
            }
        }
        cpa_commit();
    };

    float acc[2][8][4];
#pragma unroll
    for (int mi = 0; mi < 2; mi++)
#pragma unroll
        for (int ni = 0; ni < 8; ni++)
#pragma unroll
            for (int q = 0; q < 4; q++) acc[mi][ni][q] = 0.f;

    // per-lane ldmatrix row offsets (bytes), before swizzle
    uint32_t a_ro = (uint32_t)((lane & 15) << 7) + (uint32_t)((lane >> 4) << 4);
    // B: row = wn*64 + j*16 + ((lane>>4)<<3) + (lane&7); col8 = ((lane>>3)&1)*8 halfs
    uint32_t b_row_base = (uint32_t)(wn * 64 + ((lane >> 4) << 3) + (lane & 7));
    uint32_t b_co = (uint32_t)(((lane >> 3) & 1) << 4);   // bytes

    const int KT = KDIM / BKH;
    load_stage(0, 0);

    for (int it = 0; it < KT; it++) {
        int s = it & 1;
        if (it + 1 < KT) {
            load_stage(s ^ 1, (it + 1) * BKH);
            cpa_wait<1>();
        } else {
            cpa_wait<0>();
        }
        __syncthreads();

        uint32_t sA = sb + s * A_STAGE;
        uint32_t sB = sb + 2 * A_STAGE + s * B_STAGE;

#pragma unroll
        for (int k0 = 0; k0 < BKH; k0 += 16) {
            uint32_t a[2][4];
#pragma unroll
            for (int mi = 0; mi < 2; mi++) {
                uint32_t off = a_ro + (uint32_t)((wm * 32 + mi * 16) << 7) + (uint32_t)(k0 << 1);
                ldsm4(a[mi][0], a[mi][1], a[mi][2], a[mi][3], sA + swz(off));
            }
            uint32_t b[8][2];
#pragma unroll
            for (int j = 0; j < 4; j++) {
                uint32_t off = ((b_row_base + j * 16) << 7) + b_co + (uint32_t)(k0 << 1);
                uint32_t r0, r1, r2, r3;
                ldsm4(r0, r1, r2, r3, sB + swz(off));
                b[2*j][0] = r0; b[2*j][1] = r1;
                b[2*j+1][0] = r2; b[2*j+1][1] = r3;
            }
#pragma unroll
            for (int mi = 0; mi < 2; mi++)
#pragma unroll
                for (int ni = 0; ni < 8; ni++)
                    mma16(acc[mi][ni], a[mi], b[ni][0], b[ni][1]);
        }
        __syncthreads();
    }

    // epilogue: bias (+ exact gelu, fp16 store) for GEMM1; fp32 store for GEMM2
    const float* bp = bias + (size_t)e * NDIM + n0;
#pragma unroll
    for (int mi = 0; mi < 2; mi++) {
#pragma unroll
        for (int rr = 0; rr < 2; rr++) {
            int row = row0 + wm * 32 + mi * 16 + g + rr * 8;
#pragma unroll
            for (int ni = 0; ni < 8; ni++) {
                int col = wn * 64 + ni * 8 + 2 * tg;
                float v0 = acc[mi][ni][2 * rr]     + bp[col];
                float v1 = acc[mi][ni][2 * rr + 1] + bp[col + 1];
                if (FIRST) {
                    __half2 h = __floats2half2_rn(gelu_exact(v0), gelu_exact(v1));
                    *(__half2*)((__half*)OutP + (size_t)row * NDIM + n0 + col) = h;
                } else {
                    float2 o; o.x = v0; o.y = v1;
                    *(float2*)((float*)OutP + (size_t)row * NDIM + n0 + col) = o;
                }
            }
        }
    }
}

// -------------------- combine --------------------
__global__ void k_combine(float* __restrict__ out) {
    int i = blockIdx.x * blockDim.x + threadIdx.x;
    if (i >= N_TOK * (CDIM / 4)) return;
    int t = i / (CDIM / 4);
    int c = (i % (CDIM / 4)) * 4;
    int s0 = g_tok_slot[2 * t], s1 = g_tok_slot[2 * t + 1];
    float w0 = g_wt[2 * t], w1 = g_wt[2 * t + 1];
    float4 y0 = *(const float4*)(g_y + (size_t)s0 * CDIM + c);
    float4 y1 = *(const float4*)(g_y + (size_t)s1 * CDIM + c);
    float4 o;
    o.x = w0 * y0.x + w1 * y1.x;
    o.y = w0 * y0.y + w1 * y1.y;
    o.z = w0 * y0.z + w1 * y1.z;
    o.w = w0 * y0.w + w1 * y1.w;
    *(float4*)(out + (size_t)t * CDIM + c) = o;
}

// -------------------- launch --------------------
extern "C" void kernel_launch(void* const* d_in, const int* in_sizes, int n_in,
                              void* d_out, int out_size) {
    const float* x  = (const float*)d_in[0];
    const float* rw = (const float*)d_in[1];
    const float* rb = (const float*)d_in[2];
    const float* w1 = (const float*)d_in[3];
    const float* b1 = (const float*)d_in[4];
    const float* w2 = (const float*)d_in[5];
    const float* b2 = (const float*)d_in[6];
    float* out = (float*)d_out;

    cudaFuncSetAttribute(hgemm<CDIM, DFF,  true >,
                         cudaFuncAttributeMaxDynamicSharedMemorySize, SMEM_DYN);
    cudaFuncSetAttribute(hgemm<DFF,  CDIM, false>,
                         cudaFuncAttributeMaxDynamicSharedMemorySize, SMEM_DYN);

    __half* w1t; cudaGetSymbolAddress((void**)&w1t, g_w1t);
    __half* w2t; cudaGetSymbolAddress((void**)&w2t, g_w2t);
    __half* a0;  cudaGetSymbolAddress((void**)&a0,  g_A0h);
    __half* h;   cudaGetSymbolAddress((void**)&h,   g_h);
    float*  y;   cudaGetSymbolAddress((void**)&y,   g_y);

    k_init<<<(SLOT_CAP + 255) / 256, 256>>>();
    k_router<<<N_TOK / 8, 256>>>(x, rw, rb);
    k_sched<<<1, 1>>>();
    k_scatter<<<(2 * N_TOK + 255) / 256, 256>>>();
    k_gather<<<SLOT_CAP, 256>>>(x);
    k_wcvt<<<dim3(DFF / 32, CDIM / 32, NEXP), dim3(32, 8)>>>(w1, w1t, CDIM, DFF);
    k_wcvt<<<dim3(CDIM / 32, DFF / 32, NEXP), dim3(32, 8)>>>(w2, w2t, DFF, CDIM);

    hgemm<CDIM, DFF,  true ><<<dim3(MAX_TILES, DFF / BN), 256, SMEM_DYN>>>(a0, w1t, b1, h);
    hgemm<DFF,  CDIM, false><<<dim3(MAX_TILES, CDIM / BN), 256, SMEM_DYN>>>(h,  w2t, b2, y);

    k_combine<<<(N_TOK * (CDIM / 4) + 255) / 256, 256>>>(out);
}